// round 1
// baseline (speedup 1.0000x reference)
#include <cuda_runtime.h>
#include <cstdint>

#define BATCH 512
#define GS 2048
#define PARAM 64
#define OGS 1024
#define KDIM 128   // PARAM * C
#define NDIM 64    // PARAMO
#define TILE_ROWS 128
#define APAD 132   // padded K-stride for As (kills bank conflicts, keeps 16B align)

// Scratch for sorted order indices (device global: allocation-free).
__device__ unsigned int g_order[BATCH * GS];

// ---------------------------------------------------------------------------
// Kernel 1: per-batch descending sort by x[b, i, PARAM-1], stable in index.
// Bitonic sort of packed u64 keys: high 32 = ~monotone(float) (so ascending
// u64 order == descending float order), low 32 = index (ascending tie-break,
// matching jax.lax.top_k stability).
// ---------------------------------------------------------------------------
__global__ __launch_bounds__(1024) void sort_kernel(const float* __restrict__ x) {
    __shared__ unsigned long long keys[GS];
    const int b = blockIdx.x;
    const int t = threadIdx.x;
    const float* xb = x + (size_t)b * GS * PARAM;

    #pragma unroll
    for (int i = t; i < GS; i += 1024) {
        float v = xb[(size_t)i * PARAM + (PARAM - 1)];
        unsigned int u = __float_as_uint(v);
        unsigned int m = (u & 0x80000000u) ? ~u : (u | 0x80000000u); // ascending monotone
        unsigned int kk = ~m;                                        // descending
        keys[i] = ((unsigned long long)kk << 32) | (unsigned int)i;
    }
    __syncthreads();

    // GS/2 = 1024 compares per phase, exactly one per thread.
    for (int k = 2; k <= GS; k <<= 1) {
        for (int j = k >> 1; j > 0; j >>= 1) {
            int i = ((t & ~(j - 1)) << 1) | (t & (j - 1));
            int partner = i | j;
            bool up = ((i & k) == 0);
            unsigned long long a = keys[i];
            unsigned long long c = keys[partner];
            if ((a > c) == up) { keys[i] = c; keys[partner] = a; }
            __syncthreads();
        }
    }

    #pragma unroll
    for (int i = t; i < GS; i += 1024)
        g_order[b * GS + i] = (unsigned int)(keys[i] & 0xffffffffu);
}

// ---------------------------------------------------------------------------
// Kernel 2: gather + GEMM.
// Block = (batch b, tile of TILE_ROWS=128 output rows). 256 threads.
//   As[128][APAD] : 128 gathered input rows of K=128 (concat of 2 x-rows each)
//   Bs[128][64]   : full trafo
// Thread (ty=t/8, tx=t%8) computes rows ty*4..+3, cols tx*8..+7 using packed
// fma.rn.f32x2 (FFMA2: rt=2 for 2 FMAs — 2x scalar FFMA throughput on B300).
// ---------------------------------------------------------------------------
__global__ __launch_bounds__(256) void gemm_kernel(const float* __restrict__ x,
                                                   const float* __restrict__ trafo,
                                                   float* __restrict__ out) {
    extern __shared__ float smem[];
    float* As = smem;                       // TILE_ROWS * APAD floats
    float* Bs = smem + TILE_ROWS * APAD;    // KDIM * NDIM floats

    const int b = blockIdx.y;
    const int tileRow = blockIdx.x * TILE_ROWS;
    const int t = threadIdx.x;

    // Load trafo (8192 floats) via float4: 256 threads x 8 iters.
    {
        const float4* tf4 = (const float4*)trafo;
        float4* Bs4 = (float4*)Bs;
        #pragma unroll
        for (int i = 0; i < (KDIM * NDIM / 4) / 256; i++)
            Bs4[t + 256 * i] = tf4[t + 256 * i];
    }

    // Gather 256 source x-rows. Source row s uses index
    // g_order[b*GS + 2*tileRow + s]  (consecutive!), lands at
    // As[s/2][(s%2)*64 ...]. 16 threads cooperate per row (16B each).
    {
        const float* xb = x + (size_t)b * GS * PARAM;
        const int lane16 = t & 15;
        const int base = b * GS + 2 * tileRow;
        #pragma unroll
        for (int pass = 0; pass < 16; pass++) {
            int s = pass * 16 + (t >> 4);
            unsigned int idx = g_order[base + s];
            float4 v = ((const float4*)(xb + (size_t)idx * PARAM))[lane16];
            int r = s >> 1;
            int off = (s & 1) * PARAM + lane16 * 4;
            *(float4*)(As + r * APAD + off) = v;
        }
    }
    __syncthreads();

    const int tx = t & 7;       // col group: cols tx*8 .. tx*8+7
    const int ty = t >> 3;      // row group: rows ty*4 .. ty*4+3
    const int row0 = ty * 4;

    unsigned long long acc[4][4];
    #pragma unroll
    for (int r = 0; r < 4; r++)
        #pragma unroll
        for (int p = 0; p < 4; p++) acc[r][p] = 0ull;

    #pragma unroll 4
    for (int k = 0; k < KDIM; k++) {
        unsigned long long av[4];
        #pragma unroll
        for (int r = 0; r < 4; r++) {
            float a = As[(row0 + r) * APAD + k];
            asm("mov.b64 %0, {%1, %1};" : "=l"(av[r]) : "f"(a));
        }
        unsigned long long bv[4];
        {
            ulonglong2 q0 = *(const ulonglong2*)(Bs + k * NDIM + tx * 8);
            ulonglong2 q1 = *(const ulonglong2*)(Bs + k * NDIM + tx * 8 + 4);
            bv[0] = q0.x; bv[1] = q0.y; bv[2] = q1.x; bv[3] = q1.y;
        }
        #pragma unroll
        for (int r = 0; r < 4; r++)
            #pragma unroll
            for (int p = 0; p < 4; p++)
                asm("fma.rn.f32x2 %0, %1, %2, %0;"
                    : "+l"(acc[r][p]) : "l"(av[r]), "l"(bv[p]));
    }

    // Epilogue: 4 rows x 8 cols per thread, two float4 stores per row.
    float* outp = out + ((size_t)b * OGS + tileRow) * NDIM;
    #pragma unroll
    for (int r = 0; r < 4; r++) {
        float vals[8];
        #pragma unroll
        for (int p = 0; p < 4; p++) {
            float lo, hi;
            asm("mov.b64 {%0, %1}, %2;" : "=f"(lo), "=f"(hi) : "l"(acc[r][p]));
            vals[2 * p]     = lo;
            vals[2 * p + 1] = hi;
        }
        float* dst = outp + (size_t)(row0 + r) * NDIM + tx * 8;
        *(float4*)(dst)     = make_float4(vals[0], vals[1], vals[2], vals[3]);
        *(float4*)(dst + 4) = make_float4(vals[4], vals[5], vals[6], vals[7]);
    }
}

extern "C" void kernel_launch(void* const* d_in, const int* in_sizes, int n_in,
                              void* d_out, int out_size) {
    const float* x     = (const float*)d_in[0];
    const float* trafo = (const float*)d_in[1];
    float* out         = (float*)d_out;

    sort_kernel<<<BATCH, 1024>>>(x);

    size_t smem = (size_t)(TILE_ROWS * APAD + KDIM * NDIM) * sizeof(float); // ~98 KB
    cudaFuncSetAttribute(gemm_kernel, cudaFuncAttributeMaxDynamicSharedMemorySize,
                         (int)smem);
    dim3 grid(OGS / TILE_ROWS, BATCH);
    gemm_kernel<<<grid, 256, smem>>>(x, trafo, out);
}

// round 3
// speedup vs baseline: 3.1340x; 3.1340x over previous
#include <cuda_runtime.h>
#include <cuda_bf16.h>
#include <cstdint>

#define BATCH 512
#define GS 2048
#define PARAM 64
#define OGS 1024
#define KDIM 128
#define NDIM 64
#define TILE_ROWS 128

#define APITCH 136          // halves per A row (272B: ldmatrix conflict-free)
#define BPITCH 136
// smem byte offsets
#define OFF_AH 0
#define OFF_AL (OFF_AH + TILE_ROWS * APITCH * 2)          // 34816
#define OFF_BH (OFF_AL + TILE_ROWS * APITCH * 2)          // 69632
#define OFF_BL (OFF_BH + NDIM * BPITCH * 2)               // 87040
#define SMEM_BYTES (OFF_BL + NDIM * BPITCH * 2)           // 104448

__device__ unsigned int g_order[BATCH * GS];
__device__ __align__(16) unsigned short g_Bh[NDIM * BPITCH];
__device__ __align__(16) unsigned short g_Bl[NDIM * BPITCH];

__device__ __forceinline__ uint32_t smem_u32(const void* p) {
    uint32_t a;
    asm("{ .reg .u64 t; cvta.to.shared.u64 t, %1; cvt.u32.u64 %0, t; }" : "=r"(a) : "l"(p));
    return a;
}

#define LDM4(r, addr) \
    asm volatile("ldmatrix.sync.aligned.m8n8.x4.shared.b16 {%0,%1,%2,%3}, [%4];" \
        : "=r"((r)[0]), "=r"((r)[1]), "=r"((r)[2]), "=r"((r)[3]) : "r"(addr))

#define MMA(d, a, b0v, b1v) \
    asm volatile("mma.sync.aligned.m16n8k16.row.col.f32.bf16.bf16.f32 " \
        "{%0,%1,%2,%3},{%4,%5,%6,%7},{%8,%9},{%0,%1,%2,%3};" \
        : "+f"((d)[0]), "+f"((d)[1]), "+f"((d)[2]), "+f"((d)[3]) \
        : "r"((a)[0]), "r"((a)[1]), "r"((a)[2]), "r"((a)[3]), "r"(b0v), "r"(b1v))

// bf16 hi/lo split
__device__ __forceinline__ void bf16_split(float v, unsigned short& h, unsigned short& l) {
    __nv_bfloat16 bh = __float2bfloat16_rn(v);
    float r = v - __bfloat162float(bh);
    __nv_bfloat16 bl = __float2bfloat16_rn(r);
    h = *(unsigned short*)&bh;
    l = *(unsigned short*)&bl;
}

// ---------------------------------------------------------------------------
// Kernel 0: split trafo -> bf16 hi/lo, transpose to [n][k] padded images.
// ---------------------------------------------------------------------------
__global__ __launch_bounds__(256) void bsetup_kernel(const float* __restrict__ trafo) {
    for (int i = threadIdx.x; i < KDIM * NDIM; i += 256) {
        int n = i & 63, k = i >> 6;
        unsigned short h, l;
        bf16_split(trafo[k * NDIM + n], h, l);
        g_Bh[n * BPITCH + k] = h;
        g_Bl[n * BPITCH + k] = l;
    }
}

// ---------------------------------------------------------------------------
// Kernel 1: hybrid bitonic sort. 2 keys/thread in registers; phases k<=64
// fully via shfl (no barriers); only stages j>=64 go through smem.
// ---------------------------------------------------------------------------
__global__ __launch_bounds__(1024) void sort_kernel(const float* __restrict__ x) {
    __shared__ unsigned long long keys[GS];
    const int b = blockIdx.x;
    const int t = threadIdx.x;
    const float* xb = x + (size_t)b * GS * PARAM;

    unsigned long long K0, K1;
    {
        unsigned u0 = __float_as_uint(xb[(size_t)(2 * t) * PARAM + (PARAM - 1)]);
        unsigned u1 = __float_as_uint(xb[(size_t)(2 * t + 1) * PARAM + (PARAM - 1)]);
        unsigned m0 = (u0 & 0x80000000u) ? ~u0 : (u0 | 0x80000000u);
        unsigned m1 = (u1 & 0x80000000u) ? ~u1 : (u1 | 0x80000000u);
        K0 = ((unsigned long long)(~m0) << 32) | (unsigned)(2 * t);
        K1 = ((unsigned long long)(~m1) << 32) | (unsigned)(2 * t + 1);
    }

    #pragma unroll
    for (int k = 2; k <= 64; k <<= 1) {
        bool up = (((2 * t) & k) == 0);
        #pragma unroll
        for (int j = k >> 1; j >= 2; j >>= 1) {
            unsigned long long P0 = __shfl_xor_sync(0xffffffffu, K0, j >> 1);
            unsigned long long P1 = __shfl_xor_sync(0xffffffffu, K1, j >> 1);
            bool keepmin = (((t & (j >> 1)) == 0) == up);
            K0 = keepmin ? (K0 < P0 ? K0 : P0) : (K0 > P0 ? K0 : P0);
            K1 = keepmin ? (K1 < P1 ? K1 : P1) : (K1 > P1 ? K1 : P1);
        }
        if ((K0 > K1) == up) { unsigned long long tmp = K0; K0 = K1; K1 = tmp; }
    }
    keys[2 * t] = K0; keys[2 * t + 1] = K1;
    __syncthreads();

    for (int k = 128; k <= GS; k <<= 1) {
        for (int j = k >> 1; j >= 64; j >>= 1) {
            int i = ((t & ~(j - 1)) << 1) | (t & (j - 1));
            bool up2 = ((i & k) == 0);
            unsigned long long a = keys[i];
            unsigned long long c = keys[i | j];
            if ((a > c) == up2) { keys[i] = c; keys[i | j] = a; }
            __syncthreads();
        }
        K0 = keys[2 * t]; K1 = keys[2 * t + 1];
        bool up = (((2 * t) & k) == 0);
        #pragma unroll
        for (int j = 32; j >= 2; j >>= 1) {
            unsigned long long P0 = __shfl_xor_sync(0xffffffffu, K0, j >> 1);
            unsigned long long P1 = __shfl_xor_sync(0xffffffffu, K1, j >> 1);
            bool keepmin = (((t & (j >> 1)) == 0) == up);
            K0 = keepmin ? (K0 < P0 ? K0 : P0) : (K0 > P0 ? K0 : P0);
            K1 = keepmin ? (K1 < P1 ? K1 : P1) : (K1 > P1 ? K1 : P1);
        }
        if ((K0 > K1) == up) { unsigned long long tmp = K0; K0 = K1; K1 = tmp; }
        if (k < GS) {
            keys[2 * t] = K0; keys[2 * t + 1] = K1;
            __syncthreads();
        }
    }

    g_order[b * GS + 2 * t]     = (unsigned)(K0 & 0xffffffffu);
    g_order[b * GS + 2 * t + 1] = (unsigned)(K1 & 0xffffffffu);
}

// ---------------------------------------------------------------------------
// Kernel 2: fused gather + 3-term bf16 mma.sync GEMM (M128 N64 K128 per CTA).
// 8 warps: warp w -> rows (w&3)*32, cols (w>>2)*32.
// ---------------------------------------------------------------------------
__global__ __launch_bounds__(256, 2) void gemm_kernel(const float* __restrict__ x,
                                                      float* __restrict__ out) {
    extern __shared__ char smem[];
    unsigned short* Ah = (unsigned short*)(smem + OFF_AH);
    unsigned short* Al = (unsigned short*)(smem + OFF_AL);

    const int b = blockIdx.y;
    const int tileRow = blockIdx.x * TILE_ROWS;
    const int t = threadIdx.x;
    const int wid = t >> 5;
    const int lid = t & 31;

    // Copy pre-split B images (L2-hot) into smem: 2 x 1088 uint4.
    {
        const uint4* sh = (const uint4*)g_Bh;
        const uint4* sl = (const uint4*)g_Bl;
        uint4* dh = (uint4*)(smem + OFF_BH);
        uint4* dl = (uint4*)(smem + OFF_BL);
        #pragma unroll
        for (int i = t; i < NDIM * BPITCH * 2 / 16; i += 256) {
            dh[i] = sh[i];
            dl[i] = sl[i];
        }
    }

    // Gather 256 x-rows, split to bf16 hi/lo tiles.
    {
        const float* xb = x + (size_t)b * GS * PARAM;
        const int lane16 = t & 15;
        const int base = b * GS + 2 * tileRow;
        #pragma unroll
        for (int pass = 0; pass < 16; pass++) {
            int s = pass * 16 + (t >> 4);
            unsigned idx = g_order[base + s];
            float4 v = ((const float4*)(xb + (size_t)idx * PARAM))[lane16];
            int r = s >> 1;
            int koff = (s & 1) * PARAM + lane16 * 4;
            unsigned short h[4], l[4];
            bf16_split(v.x, h[0], l[0]);
            bf16_split(v.y, h[1], l[1]);
            bf16_split(v.z, h[2], l[2]);
            bf16_split(v.w, h[3], l[3]);
            uint2 hp, lp;
            hp.x = (uint32_t)h[0] | ((uint32_t)h[1] << 16);
            hp.y = (uint32_t)h[2] | ((uint32_t)h[3] << 16);
            lp.x = (uint32_t)l[0] | ((uint32_t)l[1] << 16);
            lp.y = (uint32_t)l[2] | ((uint32_t)l[3] << 16);
            *(uint2*)(Ah + r * APITCH + koff) = hp;
            *(uint2*)(Al + r * APITCH + koff) = lp;
        }
    }
    __syncthreads();

    const int wm = (wid & 3) * 32;
    const int wn = (wid >> 2) * 32;
    const uint32_t sb = smem_u32(smem);

    // ldmatrix lane addresses.
    // A x4: lanes 0-15 -> rows wm+l @k0 ; lanes 16-31 -> rows wm+(l-16) @k0+8
    uint32_t a_addr = sb + OFF_AH +
        (((uint32_t)(wm + (lid & 15)) * APITCH + (uint32_t)((lid >> 4) * 8)) << 1);
    // B x4: lanes 0-7 rows wn+l @k0; 8-15 same rows @k0+8; 16-23 rows+8 @k0; 24-31 rows+8 @k0+8
    uint32_t b_addr = sb + OFF_BH +
        (((uint32_t)(wn + (lid & 7) + ((lid >> 4) << 3)) * BPITCH +
          (uint32_t)(((lid >> 3) & 1) * 8)) << 1);

    const uint32_t A_LO = OFF_AL - OFF_AH;     // byte delta hi->lo
    const uint32_t B_LO = OFF_BL - OFF_BH;
    const uint32_t A_MT = 16 * APITCH * 2;     // +16 rows
    const uint32_t B_NT = 16 * BPITCH * 2;     // +16 rows (nt pair 2,3)

    float d[2][4][4];
    #pragma unroll
    for (int mt = 0; mt < 2; mt++)
        #pragma unroll
        for (int nt = 0; nt < 4; nt++)
            #pragma unroll
            for (int e = 0; e < 4; e++) d[mt][nt][e] = 0.f;

    #pragma unroll
    for (int kc = 0; kc < 8; kc++) {
        const uint32_t ko = kc * 32;           // 16 halves = 32 bytes
        uint32_t ah[2][4], al[2][4];
        LDM4(ah[0], a_addr + ko);
        LDM4(ah[1], a_addr + A_MT + ko);
        LDM4(al[0], a_addr + A_LO + ko);
        LDM4(al[1], a_addr + A_LO + A_MT + ko);
        uint32_t bh[8], bl[8];
        LDM4(bh,     b_addr + ko);             // b0/b1 for nt0, nt1
        LDM4(bh + 4, b_addr + B_NT + ko);      // nt2, nt3
        LDM4(bl,     b_addr + B_LO + ko);
        LDM4(bl + 4, b_addr + B_LO + B_NT + ko);

        #pragma unroll
        for (int mt = 0; mt < 2; mt++)
            #pragma unroll
            for (int nt = 0; nt < 4; nt++) {
                MMA(d[mt][nt], ah[mt], bh[2 * nt], bh[2 * nt + 1]);  // hi*hi
                MMA(d[mt][nt], ah[mt], bl[2 * nt], bl[2 * nt + 1]);  // hi*lo
                MMA(d[mt][nt], al[mt], bh[2 * nt], bh[2 * nt + 1]);  // lo*hi
            }
    }

    // Epilogue: direct float2 stores.
    float* baseo = out + ((size_t)b * OGS + tileRow) * NDIM;
    #pragma unroll
    for (int mt = 0; mt < 2; mt++)
        #pragma unroll
        for (int nt = 0; nt < 4; nt++) {
            int r = wm + 16 * mt + (lid >> 2);
            int c = wn + 8 * nt + 2 * (lid & 3);
            *(float2*)(baseo + (size_t)r * NDIM + c) =
                make_float2(d[mt][nt][0], d[mt][nt][1]);
            *(float2*)(baseo + (size_t)(r + 8) * NDIM + c) =
                make_float2(d[mt][nt][2], d[mt][nt][3]);
        }
}

extern "C" void kernel_launch(void* const* d_in, const int* in_sizes, int n_in,
                              void* d_out, int out_size) {
    const float* x     = (const float*)d_in[0];
    const float* trafo = (const float*)d_in[1];
    float* out         = (float*)d_out;

    bsetup_kernel<<<1, 256>>>(trafo);
    sort_kernel<<<BATCH, 1024>>>(x);

    cudaFuncSetAttribute(gemm_kernel, cudaFuncAttributeMaxDynamicSharedMemorySize,
                         SMEM_BYTES);
    dim3 grid(OGS / TILE_ROWS, BATCH);
    gemm_kernel<<<grid, 256, SMEM_BYTES>>>(x, out);
}

// round 4
// speedup vs baseline: 3.2719x; 1.0440x over previous
#include <cuda_runtime.h>
#include <cuda_bf16.h>
#include <cstdint>

#define BATCH 512
#define GS 2048
#define PARAM 64
#define OGS 1024
#define KDIM 128
#define NDIM 64
#define TILE_ROWS 128

#define APITCH 136          // halves per A row (272B: ldmatrix conflict-free)
#define BPITCH 136
#define OFF_AH 0
#define OFF_AL (OFF_AH + TILE_ROWS * APITCH * 2)          // 34816
#define OFF_BH (OFF_AL + TILE_ROWS * APITCH * 2)          // 69632
#define OFF_BL (OFF_BH + NDIM * BPITCH * 2)               // 87040
#define SMEM_BYTES (OFF_BL + NDIM * BPITCH * 2)           // 104448

__device__ unsigned int g_order[BATCH * GS];

__device__ __forceinline__ uint32_t smem_u32(const void* p) {
    uint32_t a;
    asm("{ .reg .u64 t; cvta.to.shared.u64 t, %1; cvt.u32.u64 %0, t; }" : "=r"(a) : "l"(p));
    return a;
}

#define LDM4(r, addr) \
    asm volatile("ldmatrix.sync.aligned.m8n8.x4.shared.b16 {%0,%1,%2,%3}, [%4];" \
        : "=r"((r)[0]), "=r"((r)[1]), "=r"((r)[2]), "=r"((r)[3]) : "r"(addr))

#define MMA(d, a, b0v, b1v) \
    asm volatile("mma.sync.aligned.m16n8k16.row.col.f32.bf16.bf16.f32 " \
        "{%0,%1,%2,%3},{%4,%5,%6,%7},{%8,%9},{%0,%1,%2,%3};" \
        : "+f"((d)[0]), "+f"((d)[1]), "+f"((d)[2]), "+f"((d)[3]) \
        : "r"((a)[0]), "r"((a)[1]), "r"((a)[2]), "r"((a)[3]), "r"(b0v), "r"(b1v))

__device__ __forceinline__ void bf16_split(float v, unsigned short& h, unsigned short& l) {
    __nv_bfloat16 bh = __float2bfloat16_rn(v);
    float r = v - __bfloat162float(bh);
    __nv_bfloat16 bl = __float2bfloat16_rn(r);
    h = *(unsigned short*)&bh;
    l = *(unsigned short*)&bl;
}

__device__ __forceinline__ void ce(unsigned long long& a, unsigned long long& b, bool up) {
    if ((a > b) == up) { unsigned long long t = a; a = b; b = t; }
}

// ---------------------------------------------------------------------------
// Kernel 1: hybrid bitonic sort. 512 threads x 4 keys. Register/shfl phases
// handle k<=128 (and j<=64 of bigger phases) with no barriers; smem only j>=128.
// ---------------------------------------------------------------------------
__global__ __launch_bounds__(512) void sort_kernel(const float* __restrict__ x) {
    __shared__ unsigned long long keys[GS];
    const int b = blockIdx.x;
    const int t = threadIdx.x;
    const float* xb = x + (size_t)b * GS * PARAM;

    unsigned long long key[4];
    #pragma unroll
    for (int i = 0; i < 4; i++) {
        int e = 4 * t + i;
        unsigned u = __float_as_uint(xb[(size_t)e * PARAM + (PARAM - 1)]);
        unsigned m = (u & 0x80000000u) ? ~u : (u | 0x80000000u);
        key[i] = ((unsigned long long)(~m) << 32) | (unsigned)e;
    }

    // k = 2
    ce(key[0], key[1], true);
    ce(key[2], key[3], false);
    // k = 4
    {
        bool up = ((t & 1) == 0);
        ce(key[0], key[2], up); ce(key[1], key[3], up);
        ce(key[0], key[1], up); ce(key[2], key[3], up);
    }
    // k = 8 .. 128 : pure register/shfl phases (no barriers)
    #pragma unroll
    for (int k = 8; k <= 128; k <<= 1) {
        bool up = (((4 * t) & k) == 0);
        #pragma unroll
        for (int j = k >> 1; j >= 4; j >>= 1) {
            int d = j >> 2;
            bool keepmin = (((t & d) == 0) == up);
            #pragma unroll
            for (int i = 0; i < 4; i++) {
                unsigned long long p = __shfl_xor_sync(0xffffffffu, key[i], d);
                key[i] = keepmin ? (key[i] < p ? key[i] : p) : (key[i] > p ? key[i] : p);
            }
        }
        ce(key[0], key[2], up); ce(key[1], key[3], up);
        ce(key[0], key[1], up); ce(key[2], key[3], up);
    }

    // k = 256 .. 2048 : smem for j>=128, registers for j<=64
    for (int k = 256; k <= GS; k <<= 1) {
        #pragma unroll
        for (int i = 0; i < 4; i++) keys[4 * t + i] = key[i];
        __syncthreads();
        for (int j = k >> 1; j >= 128; j >>= 1) {
            #pragma unroll
            for (int q0 = 0; q0 < 2; q0++) {
                int q = t + q0 * 512;
                int i = ((q & ~(j - 1)) << 1) | (q & (j - 1));
                bool up2 = ((i & k) == 0);
                unsigned long long a = keys[i];
                unsigned long long c = keys[i | j];
                if ((a > c) == up2) { keys[i] = c; keys[i | j] = a; }
            }
            __syncthreads();
        }
        #pragma unroll
        for (int i = 0; i < 4; i++) key[i] = keys[4 * t + i];
        bool up = (((4 * t) & k) == 0);
        #pragma unroll
        for (int j = 64; j >= 4; j >>= 1) {
            int d = j >> 2;
            bool keepmin = (((t & d) == 0) == up);
            #pragma unroll
            for (int i = 0; i < 4; i++) {
                unsigned long long p = __shfl_xor_sync(0xffffffffu, key[i], d);
                key[i] = keepmin ? (key[i] < p ? key[i] : p) : (key[i] > p ? key[i] : p);
            }
        }
        ce(key[0], key[2], up); ce(key[1], key[3], up);
        ce(key[0], key[1], up); ce(key[2], key[3], up);
    }

    #pragma unroll
    for (int i = 0; i < 4; i++)
        g_order[b * GS + 4 * t + i] = (unsigned)(key[i] & 0xffffffffu);
}

// ---------------------------------------------------------------------------
// Kernel 2: fused B-split + gather + 3-term bf16 mma.sync GEMM.
// Block = (batch, 128-row tile), 256 threads, 8 warps:
// warp w -> rows (w&3)*32, cols (w>>2)*32.
// ---------------------------------------------------------------------------
__global__ __launch_bounds__(256, 2) void gemm_kernel(const float* __restrict__ x,
                                                      const float* __restrict__ trafo,
                                                      float* __restrict__ out) {
    extern __shared__ char smem[];
    unsigned short* Ah = (unsigned short*)(smem + OFF_AH);
    unsigned short* Al = (unsigned short*)(smem + OFF_AL);
    unsigned short* Bh = (unsigned short*)(smem + OFF_BH);
    unsigned short* Bl = (unsigned short*)(smem + OFF_BL);

    const int b = blockIdx.y;
    const int tileRow = blockIdx.x * TILE_ROWS;
    const int t = threadIdx.x;
    const int wid = t >> 5;
    const int lid = t & 31;

    // In-CTA B split: read raw trafo (L2-hot, 32KB), split + transpose to [n][k].
    #pragma unroll
    for (int i = t; i < KDIM * NDIM; i += 256) {
        int k = i >> 6, n = i & 63;          // trafo[k][n], coalesced LDG
        unsigned short h, l;
        bf16_split(trafo[i], h, l);
        Bh[n * BPITCH + k] = h;
        Bl[n * BPITCH + k] = l;
    }

    // Gather 256 x-rows, split to bf16 hi/lo tiles.
    {
        const float* xb = x + (size_t)b * GS * PARAM;
        const int lane16 = t & 15;
        const int base = b * GS + 2 * tileRow;
        #pragma unroll
        for (int pass = 0; pass < 16; pass++) {
            int s = pass * 16 + (t >> 4);
            unsigned idx = g_order[base + s];
            float4 v = ((const float4*)(xb + (size_t)idx * PARAM))[lane16];
            int r = s >> 1;
            int koff = (s & 1) * PARAM + lane16 * 4;
            unsigned short h[4], l[4];
            bf16_split(v.x, h[0], l[0]);
            bf16_split(v.y, h[1], l[1]);
            bf16_split(v.z, h[2], l[2]);
            bf16_split(v.w, h[3], l[3]);
            uint2 hp, lp;
            hp.x = (uint32_t)h[0] | ((uint32_t)h[1] << 16);
            hp.y = (uint32_t)h[2] | ((uint32_t)h[3] << 16);
            lp.x = (uint32_t)l[0] | ((uint32_t)l[1] << 16);
            lp.y = (uint32_t)l[2] | ((uint32_t)l[3] << 16);
            *(uint2*)(Ah + r * APITCH + koff) = hp;
            *(uint2*)(Al + r * APITCH + koff) = lp;
        }
    }
    __syncthreads();

    const int wm = (wid & 3) * 32;
    const int wn = (wid >> 2) * 32;
    const uint32_t sb = smem_u32(smem);

    uint32_t a_addr = sb + OFF_AH +
        (((uint32_t)(wm + (lid & 15)) * APITCH + (uint32_t)((lid >> 4) * 8)) << 1);
    uint32_t b_addr = sb + OFF_BH +
        (((uint32_t)(wn + (lid & 7) + ((lid >> 4) << 3)) * BPITCH +
          (uint32_t)(((lid >> 3) & 1) * 8)) << 1);

    const uint32_t A_LO = OFF_AL - OFF_AH;
    const uint32_t B_LO = OFF_BL - OFF_BH;
    const uint32_t A_MT = 16 * APITCH * 2;
    const uint32_t B_NT = 16 * BPITCH * 2;

    float d[2][4][4];
    #pragma unroll
    for (int mt = 0; mt < 2; mt++)
        #pragma unroll
        for (int nt = 0; nt < 4; nt++)
            #pragma unroll
            for (int e = 0; e < 4; e++) d[mt][nt][e] = 0.f;

    #pragma unroll
    for (int kc = 0; kc < 8; kc++) {
        const uint32_t ko = kc * 32;
        uint32_t ah[2][4], al[2][4];
        LDM4(ah[0], a_addr + ko);
        LDM4(ah[1], a_addr + A_MT + ko);
        LDM4(al[0], a_addr + A_LO + ko);
        LDM4(al[1], a_addr + A_LO + A_MT + ko);
        uint32_t bh[8], bl[8];
        LDM4(bh,     b_addr + ko);
        LDM4(bh + 4, b_addr + B_NT + ko);
        LDM4(bl,     b_addr + B_LO + ko);
        LDM4(bl + 4, b_addr + B_LO + B_NT + ko);

        #pragma unroll
        for (int mt = 0; mt < 2; mt++)
            #pragma unroll
            for (int nt = 0; nt < 4; nt++) {
                MMA(d[mt][nt], ah[mt], bh[2 * nt], bh[2 * nt + 1]);
                MMA(d[mt][nt], ah[mt], bl[2 * nt], bl[2 * nt + 1]);
                MMA(d[mt][nt], al[mt], bh[2 * nt], bh[2 * nt + 1]);
            }
    }

    float* baseo = out + ((size_t)b * OGS + tileRow) * NDIM;
    #pragma unroll
    for (int mt = 0; mt < 2; mt++)
        #pragma unroll
        for (int nt = 0; nt < 4; nt++) {
            int r = wm + 16 * mt + (lid >> 2);
            int c = wn + 8 * nt + 2 * (lid & 3);
            *(float2*)(baseo + (size_t)r * NDIM + c) =
                make_float2(d[mt][nt][0], d[mt][nt][1]);
            *(float2*)(baseo + (size_t)(r + 8) * NDIM + c) =
                make_float2(d[mt][nt][2], d[mt][nt][3]);
        }
}

extern "C" void kernel_launch(void* const* d_in, const int* in_sizes, int n_in,
                              void* d_out, int out_size) {
    const float* x     = (const float*)d_in[0];
    const float* trafo = (const float*)d_in[1];
    float* out         = (float*)d_out;

    sort_kernel<<<BATCH, 512>>>(x);

    cudaFuncSetAttribute(gemm_kernel, cudaFuncAttributeMaxDynamicSharedMemorySize,
                         SMEM_BYTES);
    dim3 grid(OGS / TILE_ROWS, BATCH);
    gemm_kernel<<<grid, 256, SMEM_BYTES>>>(x, trafo, out);
}

// round 5
// speedup vs baseline: 3.7730x; 1.1532x over previous
#include <cuda_runtime.h>
#include <cuda_bf16.h>
#include <cstdint>

#define BATCH 512
#define GS 2048
#define PARAM 64
#define OGS 1024
#define KDIM 128
#define NDIM 64
#define TILE_ROWS 128

#define APITCH 136          // halves per A row (272B: ldmatrix conflict-free)
#define OFF_AH 0
#define OFF_AL (OFF_AH + TILE_ROWS * APITCH * 2)          // 34816
#define SMEM_BYTES (OFF_AL + TILE_ROWS * APITCH * 2)      // 69632

__device__ unsigned int g_order[BATCH * GS];
// B mma-fragments, register layout: [ng(2)][kc(8)][group g(4)][lane(32)] uint4.
// g0 = bh[0..3], g1 = bh[4..7], g2 = bl[0..3], g3 = bl[4..7].
__device__ __align__(16) uint4 g_Bfrag[2 * 8 * 4 * 32];

__device__ __forceinline__ uint32_t smem_u32(const void* p) {
    uint32_t a;
    asm("{ .reg .u64 t; cvta.to.shared.u64 t, %1; cvt.u32.u64 %0, t; }" : "=r"(a) : "l"(p));
    return a;
}

#define LDM4(r, addr) \
    asm volatile("ldmatrix.sync.aligned.m8n8.x4.shared.b16 {%0,%1,%2,%3}, [%4];" \
        : "=r"((r)[0]), "=r"((r)[1]), "=r"((r)[2]), "=r"((r)[3]) : "r"(addr))

#define MMA(d, a, b0v, b1v) \
    asm volatile("mma.sync.aligned.m16n8k16.row.col.f32.bf16.bf16.f32 " \
        "{%0,%1,%2,%3},{%4,%5,%6,%7},{%8,%9},{%0,%1,%2,%3};" \
        : "+f"((d)[0]), "+f"((d)[1]), "+f"((d)[2]), "+f"((d)[3]) \
        : "r"((a)[0]), "r"((a)[1]), "r"((a)[2]), "r"((a)[3]), "r"(b0v), "r"(b1v))

__device__ __forceinline__ void bf16_split(float v, unsigned short& h, unsigned short& l) {
    __nv_bfloat16 bh = __float2bfloat16_rn(v);
    float r = v - __bfloat162float(bh);
    __nv_bfloat16 bl = __float2bfloat16_rn(r);
    h = *(unsigned short*)&bh;
    l = *(unsigned short*)&bl;
}

__device__ __forceinline__ void ce(unsigned long long& a, unsigned long long& b, bool up) {
    if ((a > b) == up) { unsigned long long t = a; a = b; b = t; }
}

// ---------------------------------------------------------------------------
// Kernel 1: hybrid bitonic sort (512 threads x 4 keys).
// Block 0 additionally precomputes the B mma-fragment table (one item/thread).
// ---------------------------------------------------------------------------
__global__ __launch_bounds__(512) void sort_kernel(const float* __restrict__ x,
                                                   const float* __restrict__ trafo) {
    __shared__ unsigned long long keys[GS];
    const int b = blockIdx.x;
    const int t = threadIdx.x;
    const float* xb = x + (size_t)b * GS * PARAM;

    if (b == 0) {
        // item: ng = t>>8, kc = (t>>5)&7, lane = t&31
        int ng = t >> 8;
        int kc = (t >> 5) & 7;
        int lane = t & 31;
        int n_base = ng * 32 + (lane >> 2);
        int k_base = kc * 16 + 2 * (lane & 3);
        uint32_t rh[8], rl[8];
        #pragma unroll
        for (int nt = 0; nt < 4; nt++)
            #pragma unroll
            for (int r = 0; r < 2; r++) {
                int n = n_base + 8 * nt;
                int k = k_base + 8 * r;
                unsigned short h0, l0, h1, l1;
                bf16_split(trafo[k * NDIM + n], h0, l0);
                bf16_split(trafo[(k + 1) * NDIM + n], h1, l1);
                rh[2 * nt + r] = (uint32_t)h0 | ((uint32_t)h1 << 16);
                rl[2 * nt + r] = (uint32_t)l0 | ((uint32_t)l1 << 16);
            }
        uint4* dst = g_Bfrag + (ng * 8 + kc) * 128 + lane;
        dst[0]  = make_uint4(rh[0], rh[1], rh[2], rh[3]);
        dst[32] = make_uint4(rh[4], rh[5], rh[6], rh[7]);
        dst[64] = make_uint4(rl[0], rl[1], rl[2], rl[3]);
        dst[96] = make_uint4(rl[4], rl[5], rl[6], rl[7]);
    }

    unsigned long long key[4];
    #pragma unroll
    for (int i = 0; i < 4; i++) {
        int e = 4 * t + i;
        unsigned u = __float_as_uint(xb[(size_t)e * PARAM + (PARAM - 1)]);
        unsigned m = (u & 0x80000000u) ? ~u : (u | 0x80000000u);
        key[i] = ((unsigned long long)(~m) << 32) | (unsigned)e;
    }

    ce(key[0], key[1], true);
    ce(key[2], key[3], false);
    {
        bool up = ((t & 1) == 0);
        ce(key[0], key[2], up); ce(key[1], key[3], up);
        ce(key[0], key[1], up); ce(key[2], key[3], up);
    }
    #pragma unroll
    for (int k = 8; k <= 128; k <<= 1) {
        bool up = (((4 * t) & k) == 0);
        #pragma unroll
        for (int j = k >> 1; j >= 4; j >>= 1) {
            int d = j >> 2;
            bool keepmin = (((t & d) == 0) == up);
            #pragma unroll
            for (int i = 0; i < 4; i++) {
                unsigned long long p = __shfl_xor_sync(0xffffffffu, key[i], d);
                key[i] = keepmin ? (key[i] < p ? key[i] : p) : (key[i] > p ? key[i] : p);
            }
        }
        ce(key[0], key[2], up); ce(key[1], key[3], up);
        ce(key[0], key[1], up); ce(key[2], key[3], up);
    }

    for (int k = 256; k <= GS; k <<= 1) {
        #pragma unroll
        for (int i = 0; i < 4; i++) keys[4 * t + i] = key[i];
        __syncthreads();
        for (int j = k >> 1; j >= 128; j >>= 1) {
            #pragma unroll
            for (int q0 = 0; q0 < 2; q0++) {
                int q = t + q0 * 512;
                int i = ((q & ~(j - 1)) << 1) | (q & (j - 1));
                bool up2 = ((i & k) == 0);
                unsigned long long a = keys[i];
                unsigned long long c = keys[i | j];
                if ((a > c) == up2) { keys[i] = c; keys[i | j] = a; }
            }
            __syncthreads();
        }
        #pragma unroll
        for (int i = 0; i < 4; i++) key[i] = keys[4 * t + i];
        bool up = (((4 * t) & k) == 0);
        #pragma unroll
        for (int j = 64; j >= 4; j >>= 1) {
            int d = j >> 2;
            bool keepmin = (((t & d) == 0) == up);
            #pragma unroll
            for (int i = 0; i < 4; i++) {
                unsigned long long p = __shfl_xor_sync(0xffffffffu, key[i], d);
                key[i] = keepmin ? (key[i] < p ? key[i] : p) : (key[i] > p ? key[i] : p);
            }
        }
        ce(key[0], key[2], up); ce(key[1], key[3], up);
        ce(key[0], key[1], up); ce(key[2], key[3], up);
    }

    #pragma unroll
    for (int i = 0; i < 4; i++)
        g_order[b * GS + 4 * t + i] = (unsigned)(key[i] & 0xffffffffu);
}

// ---------------------------------------------------------------------------
// Kernel 2: fused gather + 3-term bf16 mma.sync GEMM. A in smem (hi/lo tiles),
// B fragments streamed from the precomputed gmem table (L2-hot, coalesced).
// 8 warps: warp w -> rows (w&3)*32, cols (w>>2)*32. 3 CTAs/SM target.
// ---------------------------------------------------------------------------
__global__ __launch_bounds__(256, 3) void gemm_kernel(const float* __restrict__ x,
                                                      float* __restrict__ out) {
    extern __shared__ char smem[];
    unsigned short* Ah = (unsigned short*)(smem + OFF_AH);
    unsigned short* Al = (unsigned short*)(smem + OFF_AL);

    const int b = blockIdx.y;
    const int tileRow = blockIdx.x * TILE_ROWS;
    const int t = threadIdx.x;
    const int wid = t >> 5;
    const int lid = t & 31;

    // Gather 256 x-rows, split to bf16 hi/lo tiles.
    {
        const float* xb = x + (size_t)b * GS * PARAM;
        const int lane16 = t & 15;
        const int base = b * GS + 2 * tileRow;
        #pragma unroll
        for (int pass = 0; pass < 16; pass++) {
            int s = pass * 16 + (t >> 4);
            unsigned idx = g_order[base + s];
            float4 v = ((const float4*)(xb + (size_t)idx * PARAM))[lane16];
            int r = s >> 1;
            int koff = (s & 1) * PARAM + lane16 * 4;
            unsigned short h[4], l[4];
            bf16_split(v.x, h[0], l[0]);
            bf16_split(v.y, h[1], l[1]);
            bf16_split(v.z, h[2], l[2]);
            bf16_split(v.w, h[3], l[3]);
            uint2 hp, lp;
            hp.x = (uint32_t)h[0] | ((uint32_t)h[1] << 16);
            hp.y = (uint32_t)h[2] | ((uint32_t)h[3] << 16);
            lp.x = (uint32_t)l[0] | ((uint32_t)l[1] << 16);
            lp.y = (uint32_t)l[2] | ((uint32_t)l[3] << 16);
            *(uint2*)(Ah + r * APITCH + koff) = hp;
            *(uint2*)(Al + r * APITCH + koff) = lp;
        }
    }
    __syncthreads();

    const int wm = (wid & 3) * 32;
    const int ng = wid >> 2;               // B column group (0 or 1)
    const uint32_t sb = smem_u32(smem);

    uint32_t a_addr = sb + OFF_AH +
        (((uint32_t)(wm + (lid & 15)) * APITCH + (uint32_t)((lid >> 4) * 8)) << 1);
    const uint32_t A_LO = OFF_AL - OFF_AH;
    const uint32_t A_MT = 16 * APITCH * 2;

    const uint4* Bf = g_Bfrag + ng * (8 * 128) + lid;

    float d[2][4][4];
    #pragma unroll
    for (int mt = 0; mt < 2; mt++)
        #pragma unroll
        for (int nt = 0; nt < 4; nt++)
            #pragma unroll
            for (int e = 0; e < 4; e++) d[mt][nt][e] = 0.f;

    #pragma unroll
    for (int kc = 0; kc < 8; kc++) {
        const uint32_t ko = kc * 32;
        uint4 f0 = __ldg(Bf + kc * 128);          // bh[0..3]
        uint4 f1 = __ldg(Bf + kc * 128 + 32);     // bh[4..7]
        uint4 f2 = __ldg(Bf + kc * 128 + 64);     // bl[0..3]
        uint4 f3 = __ldg(Bf + kc * 128 + 96);     // bl[4..7]
        uint32_t ah[2][4], al[2][4];
        LDM4(ah[0], a_addr + ko);
        LDM4(ah[1], a_addr + A_MT + ko);
        LDM4(al[0], a_addr + A_LO + ko);
        LDM4(al[1], a_addr + A_LO + A_MT + ko);

        #pragma unroll
        for (int mt = 0; mt < 2; mt++) {
            MMA(d[mt][0], ah[mt], f0.x, f0.y);
            MMA(d[mt][1], ah[mt], f0.z, f0.w);
            MMA(d[mt][2], ah[mt], f1.x, f1.y);
            MMA(d[mt][3], ah[mt], f1.z, f1.w);
            MMA(d[mt][0], ah[mt], f2.x, f2.y);
            MMA(d[mt][1], ah[mt], f2.z, f2.w);
            MMA(d[mt][2], ah[mt], f3.x, f3.y);
            MMA(d[mt][3], ah[mt], f3.z, f3.w);
            MMA(d[mt][0], al[mt], f0.x, f0.y);
            MMA(d[mt][1], al[mt], f0.z, f0.w);
            MMA(d[mt][2], al[mt], f1.x, f1.y);
            MMA(d[mt][3], al[mt], f1.z, f1.w);
        }
    }

    float* baseo = out + ((size_t)b * OGS + tileRow) * NDIM;
    const int wn = ng * 32;
    #pragma unroll
    for (int mt = 0; mt < 2; mt++)
        #pragma unroll
        for (int nt = 0; nt < 4; nt++) {
            int r = wm + 16 * mt + (lid >> 2);
            int c = wn + 8 * nt + 2 * (lid & 3);
            *(float2*)(baseo + (size_t)r * NDIM + c) =
                make_float2(d[mt][nt][0], d[mt][nt][1]);
            *(float2*)(baseo + (size_t)(r + 8) * NDIM + c) =
                make_float2(d[mt][nt][2], d[mt][nt][3]);
        }
}

extern "C" void kernel_launch(void* const* d_in, const int* in_sizes, int n_in,
                              void* d_out, int out_size) {
    const float* x     = (const float*)d_in[0];
    const float* trafo = (const float*)d_in[1];
    float* out         = (float*)d_out;

    sort_kernel<<<BATCH, 512>>>(x, trafo);

    cudaFuncSetAttribute(gemm_kernel, cudaFuncAttributeMaxDynamicSharedMemorySize,
                         SMEM_BYTES);
    dim3 grid(OGS / TILE_ROWS, BATCH);
    gemm_kernel<<<grid, 256, SMEM_BYTES>>>(x, out);
}

// round 6
// speedup vs baseline: 3.8767x; 1.0275x over previous
#include <cuda_runtime.h>
#include <cuda_bf16.h>
#include <cstdint>

#define BATCH 512
#define GS 2048
#define PARAM 64
#define OGS 1024
#define KDIM 128
#define NDIM 64
#define TILE_ROWS 128

#define APITCH 136          // halves per A row (272B: ldmatrix conflict-free)
#define OFF_AH 0
#define OFF_AL (OFF_AH + TILE_ROWS * APITCH * 2)          // 34816
#define SMEM_BYTES (OFF_AL + TILE_ROWS * APITCH * 2)      // 69632

__device__ unsigned int g_order[BATCH * GS];
// B mma-fragments: [ng(2)][kc(8)][group g(4)][lane(32)] uint4.
// g0 = bh[0..3], g1 = bh[4..7], g2 = bl[0..3], g3 = bl[4..7].
__device__ __align__(16) uint4 g_Bfrag[2 * 8 * 4 * 32];

__device__ __forceinline__ uint32_t smem_u32(const void* p) {
    uint32_t a;
    asm("{ .reg .u64 t; cvta.to.shared.u64 t, %1; cvt.u32.u64 %0, t; }" : "=r"(a) : "l"(p));
    return a;
}

#define LDM4(r, addr) \
    asm volatile("ldmatrix.sync.aligned.m8n8.x4.shared.b16 {%0,%1,%2,%3}, [%4];" \
        : "=r"((r)[0]), "=r"((r)[1]), "=r"((r)[2]), "=r"((r)[3]) : "r"(addr))

#define MMA(d, a, b0v, b1v) \
    asm volatile("mma.sync.aligned.m16n8k16.row.col.f32.bf16.bf16.f32 " \
        "{%0,%1,%2,%3},{%4,%5,%6,%7},{%8,%9},{%0,%1,%2,%3};" \
        : "+f"((d)[0]), "+f"((d)[1]), "+f"((d)[2]), "+f"((d)[3]) \
        : "r"((a)[0]), "r"((a)[1]), "r"((a)[2]), "r"((a)[3]), "r"(b0v), "r"(b1v))

__device__ __forceinline__ void bf16_split(float v, unsigned short& h, unsigned short& l) {
    __nv_bfloat16 bh = __float2bfloat16_rn(v);
    float r = v - __bfloat162float(bh);
    __nv_bfloat16 bl = __float2bfloat16_rn(r);
    h = *(unsigned short*)&bh;
    l = *(unsigned short*)&bl;
}

__device__ __forceinline__ void ce(unsigned long long& a, unsigned long long& b, bool up) {
    if ((a > b) == up) { unsigned long long t = a; a = b; b = t; }
}

// In-thread bitonic merge of 8 slots (element distances 4,2,1), direction up.
__device__ __forceinline__ void merge8(unsigned long long* k, bool up) {
    ce(k[0], k[4], up); ce(k[1], k[5], up); ce(k[2], k[6], up); ce(k[3], k[7], up);
    ce(k[0], k[2], up); ce(k[1], k[3], up); ce(k[4], k[6], up); ce(k[5], k[7], up);
    ce(k[0], k[1], up); ce(k[2], k[3], up); ce(k[4], k[5], up); ce(k[6], k[7], up);
}

// ---------------------------------------------------------------------------
// Kernel 1: hybrid bitonic sort, 256 threads x 8 keys. Register/shfl phases
// cover element distance <=128; smem only for j>=256 (6 stages total).
// Block 0 additionally precomputes the B mma-fragment table.
// ---------------------------------------------------------------------------
__global__ __launch_bounds__(256) void sort_kernel(const float* __restrict__ x,
                                                   const float* __restrict__ trafo) {
    __shared__ unsigned long long keys[GS];
    const int b = blockIdx.x;
    const int t = threadIdx.x;
    const float* xb = x + (size_t)b * GS * PARAM;

    if (b == 0) {
        #pragma unroll
        for (int half = 0; half < 2; half++) {
            int it = t + 256 * half;
            int ng = it >> 8;
            int kc = (it >> 5) & 7;
            int lane = it & 31;
            int n_base = ng * 32 + (lane >> 2);
            int k_base = kc * 16 + 2 * (lane & 3);
            uint32_t rh[8], rl[8];
            #pragma unroll
            for (int nt = 0; nt < 4; nt++)
                #pragma unroll
                for (int r = 0; r < 2; r++) {
                    int n = n_base + 8 * nt;
                    int k = k_base + 8 * r;
                    unsigned short h0, l0, h1, l1;
                    bf16_split(trafo[k * NDIM + n], h0, l0);
                    bf16_split(trafo[(k + 1) * NDIM + n], h1, l1);
                    rh[2 * nt + r] = (uint32_t)h0 | ((uint32_t)h1 << 16);
                    rl[2 * nt + r] = (uint32_t)l0 | ((uint32_t)l1 << 16);
                }
            uint4* dst = g_Bfrag + (ng * 8 + kc) * 128 + lane;
            dst[0]  = make_uint4(rh[0], rh[1], rh[2], rh[3]);
            dst[32] = make_uint4(rh[4], rh[5], rh[6], rh[7]);
            dst[64] = make_uint4(rl[0], rl[1], rl[2], rl[3]);
            dst[96] = make_uint4(rl[4], rl[5], rl[6], rl[7]);
        }
    }

    unsigned long long key[8];
    #pragma unroll
    for (int i = 0; i < 8; i++) {
        int e = 8 * t + i;
        unsigned u = __float_as_uint(xb[(size_t)e * PARAM + (PARAM - 1)]);
        unsigned m = (u & 0x80000000u) ? ~u : (u | 0x80000000u);
        key[i] = ((unsigned long long)(~m) << 32) | (unsigned)e;
    }

    // k = 2: pairs (0,1)asc (2,3)desc (4,5)asc (6,7)desc
    ce(key[0], key[1], true);  ce(key[2], key[3], false);
    ce(key[4], key[5], true);  ce(key[6], key[7], false);
    // k = 4: (0-3) asc, (4-7) desc
    ce(key[0], key[2], true);  ce(key[1], key[3], true);
    ce(key[0], key[1], true);  ce(key[2], key[3], true);
    ce(key[4], key[6], false); ce(key[5], key[7], false);
    ce(key[4], key[5], false); ce(key[6], key[7], false);
    // k = 8: whole thread, direction alternates by t
    merge8(key, (t & 1) == 0);

    // k = 16 .. 2048 register/shfl phases; smem stages only when j >= 256.
    #pragma unroll
    for (int k = 16; k <= 256; k <<= 1) {
        bool up = ((t & (k >> 3)) == 0);
        #pragma unroll
        for (int j = k >> 1; j >= 8; j >>= 1) {
            int d = j >> 3;
            bool keepmin = (((t & d) == 0) == up);
            #pragma unroll
            for (int i = 0; i < 8; i++) {
                unsigned long long p = __shfl_xor_sync(0xffffffffu, key[i], d);
                key[i] = keepmin ? (key[i] < p ? key[i] : p) : (key[i] > p ? key[i] : p);
            }
        }
        merge8(key, up);
    }

    for (int k = 512; k <= GS; k <<= 1) {
        #pragma unroll
        for (int i = 0; i < 8; i++) keys[8 * t + i] = key[i];
        __syncthreads();
        for (int j = k >> 1; j >= 256; j >>= 1) {
            #pragma unroll
            for (int q0 = 0; q0 < 4; q0++) {
                int q = t + 256 * q0;
                int i = ((q & ~(j - 1)) << 1) | (q & (j - 1));
                bool up2 = ((i & k) == 0);
                unsigned long long a = keys[i];
                unsigned long long c = keys[i | j];
                if ((a > c) == up2) { keys[i] = c; keys[i | j] = a; }
            }
            __syncthreads();
        }
        #pragma unroll
        for (int i = 0; i < 8; i++) key[i] = keys[8 * t + i];
        bool up = ((t & (k >> 3)) == 0);
        #pragma unroll
        for (int j = 128; j >= 8; j >>= 1) {
            int d = j >> 3;
            bool keepmin = (((t & d) == 0) == up);
            #pragma unroll
            for (int i = 0; i < 8; i++) {
                unsigned long long p = __shfl_xor_sync(0xffffffffu, key[i], d);
                key[i] = keepmin ? (key[i] < p ? key[i] : p) : (key[i] > p ? key[i] : p);
            }
        }
        merge8(key, up);
    }

    #pragma unroll
    for (int i = 0; i < 8; i++)
        g_order[b * GS + 8 * t + i] = (unsigned)(key[i] & 0xffffffffu);
}

// ---------------------------------------------------------------------------
// Kernel 2: fused gather + 3-term bf16 mma.sync GEMM.
// 512 threads, 16 warps: warp w -> rows (w&7)*16, cols (w>>3)*32.
// 2 CTAs/SM (32 warps, occ 50%); B-frag table L1-resident (92KB L1 left).
// ---------------------------------------------------------------------------
__global__ __launch_bounds__(512, 2) void gemm_kernel(const float* __restrict__ x,
                                                      float* __restrict__ out) {
    extern __shared__ char smem[];
    unsigned short* Ah = (unsigned short*)(smem + OFF_AH);
    unsigned short* Al = (unsigned short*)(smem + OFF_AL);

    const int b = blockIdx.y;
    const int tileRow = blockIdx.x * TILE_ROWS;
    const int t = threadIdx.x;
    const int wid = t >> 5;
    const int lid = t & 31;

    // Gather 256 x-rows, split to bf16 hi/lo tiles. 8 passes x 32 rows.
    {
        const float* xb = x + (size_t)b * GS * PARAM;
        const int lane16 = t & 15;
        const int base = b * GS + 2 * tileRow;
        #pragma unroll
        for (int pass = 0; pass < 8; pass++) {
            int s = pass * 32 + (t >> 4);
            unsigned idx = g_order[base + s];
            float4 v = ((const float4*)(xb + (size_t)idx * PARAM))[lane16];
            int r = s >> 1;
            int koff = (s & 1) * PARAM + lane16 * 4;
            unsigned short h[4], l[4];
            bf16_split(v.x, h[0], l[0]);
            bf16_split(v.y, h[1], l[1]);
            bf16_split(v.z, h[2], l[2]);
            bf16_split(v.w, h[3], l[3]);
            uint2 hp, lp;
            hp.x = (uint32_t)h[0] | ((uint32_t)h[1] << 16);
            hp.y = (uint32_t)h[2] | ((uint32_t)h[3] << 16);
            lp.x = (uint32_t)l[0] | ((uint32_t)l[1] << 16);
            lp.y = (uint32_t)l[2] | ((uint32_t)l[3] << 16);
            *(uint2*)(Ah + r * APITCH + koff) = hp;
            *(uint2*)(Al + r * APITCH + koff) = lp;
        }
    }
    __syncthreads();

    const int wm = (wid & 7) * 16;         // 16-row group
    const int ng = wid >> 3;               // B column group (0 or 1)
    const uint32_t sb = smem_u32(smem);

    uint32_t a_addr = sb + OFF_AH +
        (((uint32_t)(wm + (lid & 15)) * APITCH + (uint32_t)((lid >> 4) * 8)) << 1);
    const uint32_t A_LO = OFF_AL - OFF_AH;

    const uint4* Bf = g_Bfrag + ng * (8 * 128) + lid;

    float d[4][4];
    #pragma unroll
    for (int nt = 0; nt < 4; nt++)
        #pragma unroll
        for (int e = 0; e < 4; e++) d[nt][e] = 0.f;

    #pragma unroll
    for (int kc = 0; kc < 8; kc++) {
        const uint32_t ko = kc * 32;
        uint4 f0 = __ldg(Bf + kc * 128);          // bh[0..3]
        uint4 f1 = __ldg(Bf + kc * 128 + 32);     // bh[4..7]
        uint4 f2 = __ldg(Bf + kc * 128 + 64);     // bl[0..3]
        uint4 f3 = __ldg(Bf + kc * 128 + 96);     // bl[4..7]
        uint32_t ah[4], al[4];
        LDM4(ah, a_addr + ko);
        LDM4(al, a_addr + A_LO + ko);

        MMA(d[0], ah, f0.x, f0.y);
        MMA(d[1], ah, f0.z, f0.w);
        MMA(d[2], ah, f1.x, f1.y);
        MMA(d[3], ah, f1.z, f1.w);
        MMA(d[0], ah, f2.x, f2.y);
        MMA(d[1], ah, f2.z, f2.w);
        MMA(d[2], ah, f3.x, f3.y);
        MMA(d[3], ah, f3.z, f3.w);
        MMA(d[0], al, f0.x, f0.y);
        MMA(d[1], al, f0.z, f0.w);
        MMA(d[2], al, f1.x, f1.y);
        MMA(d[3], al, f1.z, f1.w);
    }

    float* baseo = out + ((size_t)b * OGS + tileRow) * NDIM;
    const int wn = ng * 32;
    #pragma unroll
    for (int nt = 0; nt < 4; nt++) {
        int r = wm + (lid >> 2);
        int c = wn + 8 * nt + 2 * (lid & 3);
        *(float2*)(baseo + (size_t)r * NDIM + c) = make_float2(d[nt][0], d[nt][1]);
        *(float2*)(baseo + (size_t)(r + 8) * NDIM + c) = make_float2(d[nt][2], d[nt][3]);
    }
}

extern "C" void kernel_launch(void* const* d_in, const int* in_sizes, int n_in,
                              void* d_out, int out_size) {
    const float* x     = (const float*)d_in[0];
    const float* trafo = (const float*)d_in[1];
    float* out         = (float*)d_out;

    sort_kernel<<<BATCH, 256>>>(x, trafo);

    cudaFuncSetAttribute(gemm_kernel, cudaFuncAttributeMaxDynamicSharedMemorySize,
                         SMEM_BYTES);
    dim3 grid(OGS / TILE_ROWS, BATCH);
    gemm_kernel<<<grid, 512, SMEM_BYTES>>>(x, out);
}

// round 7
// speedup vs baseline: 4.0872x; 1.0543x over previous
#include <cuda_runtime.h>
#include <cuda_bf16.h>
#include <cstdint>

#define BATCH 512
#define GS 2048
#define PARAM 64
#define OGS 1024
#define KDIM 128
#define NDIM 64
#define TILE_ROWS 128

#define APITCH 136          // halves per A row (272B: ldmatrix conflict-free)
#define OFF_AH 0
#define OFF_AL (OFF_AH + TILE_ROWS * APITCH * 2)          // 34816
#define SMEM_BYTES (OFF_AL + TILE_ROWS * APITCH * 2)      // 69632

__device__ unsigned int g_order[BATCH * GS];
// B mma-fragments: [ng(2)][kc(8)][group g(4)][lane(32)] uint4.
__device__ __align__(16) uint4 g_Bfrag[2 * 8 * 4 * 32];
__device__ int g_flag[BATCH];      // zero-init; reset by last CTA each launch
__device__ int g_bflag;
__device__ unsigned int g_done;

__device__ __forceinline__ uint32_t smem_u32(const void* p) {
    uint32_t a;
    asm("{ .reg .u64 t; cvta.to.shared.u64 t, %1; cvt.u32.u64 %0, t; }" : "=r"(a) : "l"(p));
    return a;
}
__device__ __forceinline__ int ld_acquire(const int* p) {
    int v;
    asm volatile("ld.acquire.gpu.global.b32 %0, [%1];" : "=r"(v) : "l"(p) : "memory");
    return v;
}
__device__ __forceinline__ void st_release(int* p, int v) {
    asm volatile("st.release.gpu.global.b32 [%0], %1;" :: "l"(p), "r"(v) : "memory");
}

#define LDM4(r, addr) \
    asm volatile("ldmatrix.sync.aligned.m8n8.x4.shared.b16 {%0,%1,%2,%3}, [%4];" \
        : "=r"((r)[0]), "=r"((r)[1]), "=r"((r)[2]), "=r"((r)[3]) : "r"(addr))

#define MMA(d, a, b0v, b1v) \
    asm volatile("mma.sync.aligned.m16n8k16.row.col.f32.bf16.bf16.f32 " \
        "{%0,%1,%2,%3},{%4,%5,%6,%7},{%8,%9},{%0,%1,%2,%3};" \
        : "+f"((d)[0]), "+f"((d)[1]), "+f"((d)[2]), "+f"((d)[3]) \
        : "r"((a)[0]), "r"((a)[1]), "r"((a)[2]), "r"((a)[3]), "r"(b0v), "r"(b1v))

__device__ __forceinline__ void bf16_split(float v, unsigned short& h, unsigned short& l) {
    __nv_bfloat16 bh = __float2bfloat16_rn(v);
    float r = v - __bfloat162float(bh);
    __nv_bfloat16 bl = __float2bfloat16_rn(r);
    h = *(unsigned short*)&bh;
    l = *(unsigned short*)&bl;
}

__device__ __forceinline__ void ce(unsigned long long& a, unsigned long long& b, bool up) {
    if ((a > b) == up) { unsigned long long t = a; a = b; b = t; }
}

// ---------------------------------------------------------------------------
// Fused kernel. grid = (8, 512), block = 512.
//  - bid == 0  : precompute B mma-fragment table, release g_bflag
//  - bid < 512 : bitonic-sort batch `bid` (keys overlaid on A smem), release flag
//  - all       : acquire flag[y], gather batch y tile, acquire bflag, GEMM
// ---------------------------------------------------------------------------
__global__ __launch_bounds__(512, 2) void fused_kernel(const float* __restrict__ x,
                                                       const float* __restrict__ trafo,
                                                       float* __restrict__ out) {
    extern __shared__ char smem[];
    __shared__ unsigned s_last;

    const int y = blockIdx.y;
    const int bid = blockIdx.x + (y << 3);
    const int tileRow = blockIdx.x * TILE_ROWS;
    const int t = threadIdx.x;
    const int wid = t >> 5;
    const int lid = t & 31;

    // ---- B-fragment table (bid 0 only; 512 items, one per thread) ----
    if (bid == 0) {
        int ng = t >> 8;
        int kc = (t >> 5) & 7;
        int lane = t & 31;
        int n_base = ng * 32 + (lane >> 2);
        int k_base = kc * 16 + 2 * (lane & 3);
        uint32_t rh[8], rl[8];
        #pragma unroll
        for (int nt = 0; nt < 4; nt++)
            #pragma unroll
            for (int r = 0; r < 2; r++) {
                int n = n_base + 8 * nt;
                int k = k_base + 8 * r;
                unsigned short h0, l0, h1, l1;
                bf16_split(trafo[k * NDIM + n], h0, l0);
                bf16_split(trafo[(k + 1) * NDIM + n], h1, l1);
                rh[2 * nt + r] = (uint32_t)h0 | ((uint32_t)h1 << 16);
                rl[2 * nt + r] = (uint32_t)l0 | ((uint32_t)l1 << 16);
            }
        uint4* dst = g_Bfrag + (ng * 8 + kc) * 128 + lane;
        dst[0]  = make_uint4(rh[0], rh[1], rh[2], rh[3]);
        dst[32] = make_uint4(rh[4], rh[5], rh[6], rh[7]);
        dst[64] = make_uint4(rl[0], rl[1], rl[2], rl[3]);
        dst[96] = make_uint4(rl[4], rl[5], rl[6], rl[7]);
        __syncthreads();
        __threadfence();
        if (t == 0) st_release(&g_bflag, 1);
    }

    // ---- Sort batch `bid` (bid < 512): 512 threads x 4 keys ----
    if (bid < BATCH) {
        unsigned long long* keys = (unsigned long long*)smem;   // 16KB overlay
        const int sb = bid;
        const float* xb = x + (size_t)sb * GS * PARAM;

        unsigned long long key[4];
        #pragma unroll
        for (int i = 0; i < 4; i++) {
            int e = 4 * t + i;
            unsigned u = __float_as_uint(xb[(size_t)e * PARAM + (PARAM - 1)]);
            unsigned m = (u & 0x80000000u) ? ~u : (u | 0x80000000u);
            key[i] = ((unsigned long long)(~m) << 32) | (unsigned)e;
        }

        ce(key[0], key[1], true);
        ce(key[2], key[3], false);
        {
            bool up = ((t & 1) == 0);
            ce(key[0], key[2], up); ce(key[1], key[3], up);
            ce(key[0], key[1], up); ce(key[2], key[3], up);
        }
        #pragma unroll
        for (int k = 8; k <= 128; k <<= 1) {
            bool up = (((4 * t) & k) == 0);
            #pragma unroll
            for (int j = k >> 1; j >= 4; j >>= 1) {
                int d = j >> 2;
                bool keepmin = (((t & d) == 0) == up);
                #pragma unroll
                for (int i = 0; i < 4; i++) {
                    unsigned long long p = __shfl_xor_sync(0xffffffffu, key[i], d);
                    key[i] = keepmin ? (key[i] < p ? key[i] : p) : (key[i] > p ? key[i] : p);
                }
            }
            ce(key[0], key[2], up); ce(key[1], key[3], up);
            ce(key[0], key[1], up); ce(key[2], key[3], up);
        }

        for (int k = 256; k <= GS; k <<= 1) {
            #pragma unroll
            for (int i = 0; i < 4; i++) keys[4 * t + i] = key[i];
            __syncthreads();
            for (int j = k >> 1; j >= 128; j >>= 1) {
                #pragma unroll
                for (int q0 = 0; q0 < 2; q0++) {
                    int q = t + q0 * 512;
                    int i = ((q & ~(j - 1)) << 1) | (q & (j - 1));
                    bool up2 = ((i & k) == 0);
                    unsigned long long a = keys[i];
                    unsigned long long c = keys[i | j];
                    if ((a > c) == up2) { keys[i] = c; keys[i | j] = a; }
                }
                __syncthreads();
            }
            #pragma unroll
            for (int i = 0; i < 4; i++) key[i] = keys[4 * t + i];
            bool up = (((4 * t) & k) == 0);
            #pragma unroll
            for (int j = 64; j >= 4; j >>= 1) {
                int d = j >> 2;
                bool keepmin = (((t & d) == 0) == up);
                #pragma unroll
                for (int i = 0; i < 4; i++) {
                    unsigned long long p = __shfl_xor_sync(0xffffffffu, key[i], d);
                    key[i] = keepmin ? (key[i] < p ? key[i] : p) : (key[i] > p ? key[i] : p);
                }
            }
            ce(key[0], key[2], up); ce(key[1], key[3], up);
            ce(key[0], key[1], up); ce(key[2], key[3], up);
        }

        #pragma unroll
        for (int i = 0; i < 4; i++)
            g_order[sb * GS + 4 * t + i] = (unsigned)(key[i] & 0xffffffffu);

        __syncthreads();
        __threadfence();
        if (t == 0) st_release(&g_flag[sb], 1);
    }

    // ---- Wait for this batch's order (sorter bid = y <= our bid: no deadlock) ----
    if (t == 0) {
        while (ld_acquire(&g_flag[y]) == 0) __nanosleep(64);
    }
    __syncthreads();

    // ---- Gather 256 x-rows -> bf16 hi/lo A tiles ----
    unsigned short* Ah = (unsigned short*)(smem + OFF_AH);
    unsigned short* Al = (unsigned short*)(smem + OFF_AL);
    {
        const float* xb = x + (size_t)y * GS * PARAM;
        const int lane16 = t & 15;
        const int base = y * GS + 2 * tileRow;
        #pragma unroll
        for (int pass = 0; pass < 8; pass++) {
            int s = pass * 32 + (t >> 4);
            unsigned idx = g_order[base + s];
            float4 v = ((const float4*)(xb + (size_t)idx * PARAM))[lane16];
            int r = s >> 1;
            int koff = (s & 1) * PARAM + lane16 * 4;
            unsigned short h[4], l[4];
            bf16_split(v.x, h[0], l[0]);
            bf16_split(v.y, h[1], l[1]);
            bf16_split(v.z, h[2], l[2]);
            bf16_split(v.w, h[3], l[3]);
            uint2 hp, lp;
            hp.x = (uint32_t)h[0] | ((uint32_t)h[1] << 16);
            hp.y = (uint32_t)h[2] | ((uint32_t)h[3] << 16);
            lp.x = (uint32_t)l[0] | ((uint32_t)l[1] << 16);
            lp.y = (uint32_t)l[2] | ((uint32_t)l[3] << 16);
            *(uint2*)(Ah + r * APITCH + koff) = hp;
            *(uint2*)(Al + r * APITCH + koff) = lp;
        }
    }

    // ---- Wait for B-fragment table ----
    if (t == 0) {
        while (ld_acquire(&g_bflag) == 0) __nanosleep(64);
    }
    __syncthreads();

    // ---- Mainloop: 16 warps, warp w -> rows (w&7)*16, cols (w>>3)*32 ----
    const int wm = (wid & 7) * 16;
    const int ng = wid >> 3;
    const uint32_t sb32 = smem_u32(smem);

    uint32_t a_addr = sb32 + OFF_AH +
        (((uint32_t)(wm + (lid & 15)) * APITCH + (uint32_t)((lid >> 4) * 8)) << 1);
    const uint32_t A_LO = OFF_AL - OFF_AH;

    const uint4* Bf = g_Bfrag + ng * (8 * 128) + lid;

    float d[4][4];
    #pragma unroll
    for (int nt = 0; nt < 4; nt++)
        #pragma unroll
        for (int e = 0; e < 4; e++) d[nt][e] = 0.f;

    #pragma unroll
    for (int kc = 0; kc < 8; kc++) {
        const uint32_t ko = kc * 32;
        uint4 f0 = __ldg(Bf + kc * 128);
        uint4 f1 = __ldg(Bf + kc * 128 + 32);
        uint4 f2 = __ldg(Bf + kc * 128 + 64);
        uint4 f3 = __ldg(Bf + kc * 128 + 96);
        uint32_t ah[4], al[4];
        LDM4(ah, a_addr + ko);
        LDM4(al, a_addr + A_LO + ko);

        MMA(d[0], ah, f0.x, f0.y);
        MMA(d[1], ah, f0.z, f0.w);
        MMA(d[2], ah, f1.x, f1.y);
        MMA(d[3], ah, f1.z, f1.w);
        MMA(d[0], ah, f2.x, f2.y);
        MMA(d[1], ah, f2.z, f2.w);
        MMA(d[2], ah, f3.x, f3.y);
        MMA(d[3], ah, f3.z, f3.w);
        MMA(d[0], al, f0.x, f0.y);
        MMA(d[1], al, f0.z, f0.w);
        MMA(d[2], al, f1.x, f1.y);
        MMA(d[3], al, f1.z, f1.w);
    }

    float* baseo = out + ((size_t)y * OGS + tileRow) * NDIM;
    const int wn = ng * 32;
    #pragma unroll
    for (int nt = 0; nt < 4; nt++) {
        int r = wm + (lid >> 2);
        int c = wn + 8 * nt + 2 * (lid & 3);
        *(float2*)(baseo + (size_t)r * NDIM + c) = make_float2(d[nt][0], d[nt][1]);
        *(float2*)(baseo + (size_t)(r + 8) * NDIM + c) = make_float2(d[nt][2], d[nt][3]);
    }

    // ---- Flag reset by the last CTA to finish (keeps launches stateless) ----
    __syncthreads();
    if (t == 0) {
        unsigned done = atomicAdd(&g_done, 1u);
        s_last = (done == (unsigned)(8 * BATCH - 1));
    }
    __syncthreads();
    if (s_last) {
        if (t < BATCH) g_flag[t] = 0;
        if (t == 0) { g_bflag = 0; g_done = 0u; }
    }
}

extern "C" void kernel_launch(void* const* d_in, const int* in_sizes, int n_in,
                              void* d_out, int out_size) {
    const float* x     = (const float*)d_in[0];
    const float* trafo = (const float*)d_in[1];
    float* out         = (float*)d_out;

    cudaFuncSetAttribute(fused_kernel, cudaFuncAttributeMaxDynamicSharedMemorySize,
                         SMEM_BYTES);
    dim3 grid(OGS / TILE_ROWS, BATCH);
    fused_kernel<<<grid, 512, SMEM_BYTES>>>(x, trafo, out);
}